// round 1
// baseline (speedup 1.0000x reference)
#include <cuda_runtime.h>
#include <cuda_bf16.h>

#define F 128
#define MAXN 50000
#define MAXE 800000

// Scratch (static device globals — no runtime allocation)
__device__ float g_bufA[MAXN * F];
__device__ float g_bufB[MAXN * F];
__device__ int   g_rowstart[MAXN + 1];
__device__ int   g_cnt[MAXN];
__device__ int   g_csrs[MAXE];
__device__ float g_csrw[MAXE];

// ---------------- CSR build ----------------

__global__ void zero_counts_kernel(int n) {
    int i = blockIdx.x * blockDim.x + threadIdx.x;
    if (i < n) g_cnt[i] = 0;
}

__global__ void hist_kernel(const int* __restrict__ edst, int e) {
    int i = blockIdx.x * blockDim.x + threadIdx.x;
    if (i < e) atomicAdd(&g_cnt[edst[i]], 1);
}

// Single-block exclusive scan over counts -> rowstart; also zeroes counts for reuse as cursor.
__global__ void scan_kernel(int n) {
    __shared__ int sdata[1024];
    __shared__ int s_carry;
    int tid = threadIdx.x;
    if (tid == 0) s_carry = 0;
    __syncthreads();
    for (int base = 0; base < n; base += 1024) {
        int i = base + tid;
        int v = (i < n) ? g_cnt[i] : 0;
        sdata[tid] = v;
        __syncthreads();
        for (int off = 1; off < 1024; off <<= 1) {
            int t = (tid >= off) ? sdata[tid - off] : 0;
            __syncthreads();
            sdata[tid] += t;
            __syncthreads();
        }
        int carry = s_carry;
        if (i < n) {
            g_rowstart[i] = carry + sdata[tid] - v;
            g_cnt[i] = 0;
        }
        int total = sdata[1023];
        __syncthreads();  // all reads of sdata/s_carry done before update
        if (tid == 0) s_carry = carry + total;
        __syncthreads();
    }
    if (tid == 0) g_rowstart[n] = s_carry;
}

__global__ void scatter_kernel(const int* __restrict__ esrc,
                               const int* __restrict__ edst,
                               const float* __restrict__ ew, int e) {
    int i = blockIdx.x * blockDim.x + threadIdx.x;
    if (i < e) {
        int d = edst[i];
        int p = g_rowstart[d] + atomicAdd(&g_cnt[d], 1);
        g_csrs[p] = esrc[i];
        g_csrw[p] = ew[i];
    }
}

// ---------------- SpMM: Y[d] = sum_{e: dst=d} w_e * X[src_e] ----------------

__global__ void spmm_kernel(const float* __restrict__ X, float* __restrict__ Y, int n) {
    int node = blockIdx.x * blockDim.y + threadIdx.y;
    if (node >= n) return;
    int f = threadIdx.x;  // 0..127
    int beg = g_rowstart[node];
    int end = g_rowstart[node + 1];
    float acc = 0.f;
    for (int p = beg; p < end; ++p) {
        int s   = __ldg(&g_csrs[p]);
        float w = __ldg(&g_csrw[p]);
        acc += w * __ldg(&X[s * F + f]);
    }
    Y[node * F + f] = acc;
}

// ---------------- GEMM-accumulate: out(+)= X @ W_i (+ bias on first) -----------
// Tile: 128 rows x 128 cols per block, 256 threads (16x16), 8x8 micro-tile.

__global__ __launch_bounds__(256) void gemm_acc_kernel(
    const float* __restrict__ X, const float* __restrict__ W,
    const float* __restrict__ bias, float* __restrict__ out,
    int n, int first)
{
    __shared__ __align__(16) float Xs[8][132];  // [k][m], padded vs bank conflicts
    __shared__ __align__(16) float Ws[8][128];  // [k][j]
    int row0 = blockIdx.x * 128;
    int tid  = threadIdx.x;
    int ty   = tid >> 4;   // 0..15 -> row group
    int tx   = tid & 15;   // 0..15 -> col group

    float acc[8][8];
#pragma unroll
    for (int i = 0; i < 8; i++)
#pragma unroll
        for (int j = 0; j < 8; j++) acc[i][j] = 0.f;

    for (int kc = 0; kc < 128; kc += 8) {
        // load X tile [128 m][8 k] -> Xs[k][m]
#pragma unroll
        for (int t = tid; t < 1024; t += 256) {
            int m = t >> 3, k = t & 7;
            int r = row0 + m;
            Xs[k][m] = (r < n) ? __ldg(&X[r * 128 + kc + k]) : 0.f;
        }
        // load W tile [8 k][128 j] -> Ws[k][j] (fully coalesced)
#pragma unroll
        for (int t = tid; t < 1024; t += 256) {
            int k = t >> 7, j = t & 127;
            Ws[k][j] = __ldg(&W[(kc + k) * 128 + j]);
        }
        __syncthreads();
#pragma unroll
        for (int k = 0; k < 8; k++) {
            float4 a0 = *(const float4*)&Xs[k][ty * 8];
            float4 a1 = *(const float4*)&Xs[k][ty * 8 + 4];
            float4 b0 = *(const float4*)&Ws[k][tx * 8];
            float4 b1 = *(const float4*)&Ws[k][tx * 8 + 4];
            float xv[8] = {a0.x, a0.y, a0.z, a0.w, a1.x, a1.y, a1.z, a1.w};
            float wv[8] = {b0.x, b0.y, b0.z, b0.w, b1.x, b1.y, b1.z, b1.w};
#pragma unroll
            for (int i = 0; i < 8; i++)
#pragma unroll
                for (int j = 0; j < 8; j++)
                    acc[i][j] += xv[i] * wv[j];
        }
        __syncthreads();
    }

    // epilogue: accumulate into out
#pragma unroll
    for (int i = 0; i < 8; i++) {
        int r = row0 + ty * 8 + i;
        if (r < n) {
            float4* o = (float4*)&out[r * 128 + tx * 8];
            float4 v0, v1;
            if (first) {
                float4 bb0 = *(const float4*)&bias[tx * 8];
                float4 bb1 = *(const float4*)&bias[tx * 8 + 4];
                v0 = make_float4(acc[i][0] + bb0.x, acc[i][1] + bb0.y,
                                 acc[i][2] + bb0.z, acc[i][3] + bb0.w);
                v1 = make_float4(acc[i][4] + bb1.x, acc[i][5] + bb1.y,
                                 acc[i][6] + bb1.z, acc[i][7] + bb1.w);
            } else {
                float4 c0 = o[0], c1 = o[1];
                v0 = make_float4(c0.x + acc[i][0], c0.y + acc[i][1],
                                 c0.z + acc[i][2], c0.w + acc[i][3]);
                v1 = make_float4(c1.x + acc[i][4], c1.y + acc[i][5],
                                 c1.z + acc[i][6], c1.w + acc[i][7]);
            }
            o[0] = v0;
            o[1] = v1;
        }
    }
}

// ---------------- launch ----------------

extern "C" void kernel_launch(void* const* d_in, const int* in_sizes, int n_in,
                              void* d_out, int out_size) {
    const float* input = (const float*)d_in[0];
    const int*   esrc  = (const int*)d_in[1];
    const int*   edst  = (const int*)d_in[2];
    const float* ew    = (const float*)d_in[3];
    const float* W     = (const float*)d_in[4];
    const float* bias  = (const float*)d_in[5];
    float*       out   = (float*)d_out;

    int n = in_sizes[0] / F;
    int e = in_sizes[1];

    float* bufA = nullptr;
    float* bufB = nullptr;
    cudaGetSymbolAddress((void**)&bufA, g_bufA);
    cudaGetSymbolAddress((void**)&bufB, g_bufB);

    // 1) CSR build (recomputed every launch; deterministic work)
    zero_counts_kernel<<<(n + 255) / 256, 256>>>(n);
    hist_kernel<<<(e + 255) / 256, 256>>>(edst, e);
    scan_kernel<<<1, 1024>>>(n);
    scatter_kernel<<<(e + 255) / 256, 256>>>(esrc, edst, ew, e);

    // 2) alternate GEMM-accumulate and spmm, ping-ponging term buffers
    const float* X = input;
    float* bufs[2] = {bufA, bufB};
    int gemm_blocks = (n + 127) / 128;
    dim3 spmm_block(F, 4);
    int spmm_grid = (n + 3) / 4;

    for (int i = 0; i < 8; i++) {
        gemm_acc_kernel<<<gemm_blocks, 256>>>(X, W + i * 128 * 128, bias, out, n, i == 0);
        if (i < 7) {
            spmm_kernel<<<spmm_grid, spmm_block>>>(X, bufs[i & 1], n);
            X = bufs[i & 1];
        }
    }
}

// round 3
// speedup vs baseline: 2.5020x; 2.5020x over previous
#include <cuda_runtime.h>
#include <cuda_bf16.h>
#include <cstdint>

#define F 128
#define MAXN 50000
#define NPAD 50176            // MAXN rounded to multiple of 128 (GEMM tile overread pad)
#define MAXE 800000
#define NBLK 8

// ---------------- device scratch (static globals; no runtime alloc) ----------------
__device__ float g_bufA[MAXN * F];
__device__ float g_bufB[MAXN * F];
__device__ __nv_bfloat16 g_termsh[(size_t)NBLK * NPAD * F];  // hi parts of all 8 terms
__device__ __nv_bfloat16 g_termsm[(size_t)NBLK * NPAD * F];  // mid parts
__device__ int   g_rowstart[MAXN + 1];
__device__ int   g_cnt[MAXN];
__device__ int   g_csrs[MAXE];
__device__ float g_csrw[MAXE];
__device__ __nv_bfloat16 g_wth[F * NBLK * F];  // W^T hi  [128][1024] (k contiguous)
__device__ __nv_bfloat16 g_wtm[F * NBLK * F];  // W^T mid [128][1024]

// ---------------- helpers ----------------
__device__ __forceinline__ uint32_t smem_u32(const void* p) {
    uint32_t a;
    asm("{ .reg .u64 t; cvta.to.shared.u64 t, %1; cvt.u32.u64 %0, t; }" : "=r"(a) : "l"(p));
    return a;
}
__device__ __forceinline__ void ldsm4(uint32_t* r, uint32_t addr) {
    asm volatile("ldmatrix.sync.aligned.m8n8.x4.shared.b16 {%0,%1,%2,%3}, [%4];"
        : "=r"(r[0]), "=r"(r[1]), "=r"(r[2]), "=r"(r[3]) : "r"(addr));
}
__device__ __forceinline__ void mma16816(float* c, const uint32_t* a, const uint32_t* b) {
    asm volatile("mma.sync.aligned.m16n8k16.row.col.f32.bf16.bf16.f32 "
        "{%0,%1,%2,%3}, {%4,%5,%6,%7}, {%8,%9}, {%0,%1,%2,%3};"
        : "+f"(c[0]), "+f"(c[1]), "+f"(c[2]), "+f"(c[3])
        : "r"(a[0]), "r"(a[1]), "r"(a[2]), "r"(a[3]), "r"(b[0]), "r"(b[1]));
}
// split fp32 -> (hi bf16, mid bf16)
__device__ __forceinline__ void split_bf16(float x, __nv_bfloat16& h, __nv_bfloat16& m) {
    h = __float2bfloat16_rn(x);
    m = __float2bfloat16_rn(x - __bfloat162float(h));
}

// ---------------- CSR build ----------------
__global__ void zero_counts_kernel(int n) {
    int i = blockIdx.x * blockDim.x + threadIdx.x;
    if (i < n) g_cnt[i] = 0;
}
__global__ void hist_kernel(const int* __restrict__ edst, int e) {
    int i = blockIdx.x * blockDim.x + threadIdx.x;
    if (i < e) atomicAdd(&g_cnt[edst[i]], 1);
}
__global__ void scan_kernel(int n) {
    __shared__ int sdata[1024];
    __shared__ int s_carry;
    int tid = threadIdx.x;
    if (tid == 0) s_carry = 0;
    __syncthreads();
    for (int base = 0; base < n; base += 1024) {
        int i = base + tid;
        int v = (i < n) ? g_cnt[i] : 0;
        sdata[tid] = v;
        __syncthreads();
        for (int off = 1; off < 1024; off <<= 1) {
            int t = (tid >= off) ? sdata[tid - off] : 0;
            __syncthreads();
            sdata[tid] += t;
            __syncthreads();
        }
        int carry = s_carry;
        if (i < n) { g_rowstart[i] = carry + sdata[tid] - v; g_cnt[i] = 0; }
        int total = sdata[1023];
        __syncthreads();
        if (tid == 0) s_carry = carry + total;
        __syncthreads();
    }
    if (tid == 0) g_rowstart[n] = s_carry;
}
__global__ void scatter_kernel(const int* __restrict__ esrc, const int* __restrict__ edst,
                               const float* __restrict__ ew, int e) {
    int i = blockIdx.x * blockDim.x + threadIdx.x;
    if (i < e) {
        int d = edst[i];
        int p = g_rowstart[d] + atomicAdd(&g_cnt[d], 1);
        g_csrs[p] = esrc[i];
        g_csrw[p] = ew[i];
    }
}

// ---------------- W^T split to bf16 hi/mid ----------------
__global__ void wprep_kernel(const float* __restrict__ W) {  // W [1024,128]
    int i = blockIdx.x * blockDim.x + threadIdx.x;
    if (i < 1024 * 128) {
        int k = i >> 7, nn = i & 127;
        __nv_bfloat16 h, m;
        split_bf16(W[i], h, m);
        g_wth[nn * 1024 + k] = h;
        g_wtm[nn * 1024 + k] = m;
    }
}

// ---------------- term 0: convert input -> bf16 h/m ----------------
__global__ void conv0_kernel(const float* __restrict__ src,
                             __nv_bfloat16* __restrict__ th,
                             __nv_bfloat16* __restrict__ tm, int n4) {
    int i = blockIdx.x * blockDim.x + threadIdx.x;
    if (i >= n4) return;
    float4 x = ((const float4*)src)[i];
    __nv_bfloat16 h[4], m[4];
    split_bf16(x.x, h[0], m[0]); split_bf16(x.y, h[1], m[1]);
    split_bf16(x.z, h[2], m[2]); split_bf16(x.w, h[3], m[3]);
    int node = i >> 5, q = i & 31;
    size_t off = (size_t)node * 128 + q * 4;
    *(uint2*)&th[off] = *(uint2*)h;
    *(uint2*)&tm[off] = *(uint2*)m;
}

// ---------------- SpMM: Y[d] = sum w_e X[src_e]; also emit bf16 h/m ----------------
__global__ void spmm_kernel(const float* __restrict__ X, float* __restrict__ Y,
                            __nv_bfloat16* __restrict__ th,
                            __nv_bfloat16* __restrict__ tm, int n) {
    int node = blockIdx.x * blockDim.y + threadIdx.y;
    if (node >= n) return;
    int lane = threadIdx.x;  // 0..31
    int beg = g_rowstart[node], end = g_rowstart[node + 1];
    float4 acc = make_float4(0.f, 0.f, 0.f, 0.f);
    const float4* Xv = (const float4*)X;
    for (int p = beg; p < end; ++p) {
        int s = __ldg(&g_csrs[p]);
        float w = __ldg(&g_csrw[p]);
        float4 x = __ldg(&Xv[s * 32 + lane]);
        acc.x += w * x.x; acc.y += w * x.y; acc.z += w * x.z; acc.w += w * x.w;
    }
    ((float4*)Y)[node * 32 + lane] = acc;
    __nv_bfloat16 h[4], m[4];
    split_bf16(acc.x, h[0], m[0]); split_bf16(acc.y, h[1], m[1]);
    split_bf16(acc.z, h[2], m[2]); split_bf16(acc.w, h[3], m[3]);
    size_t off = (size_t)node * 128 + lane * 4;
    *(uint2*)&th[off] = *(uint2*)h;
    *(uint2*)&tm[off] = *(uint2*)m;
}

// ---------------- GEMM: out[N,128] = cat[N,1024] @ W[1024,128] + bias ----------------
// mma.sync bf16x3 (AhBh + AhBm + AmBh). CTA tile 128x128, 8 warps of 32x64.
// smem: Ah, Am, Bh, Bm tiles of [128][64] bf16, row stride 72 bf16 (144 B).
#define A_STRB 144
#define TILE_BYTES (128 * A_STRB)          // 18432 per array
#define SM_GEMM (4 * TILE_BYTES)           // 73728

__global__ void __launch_bounds__(256, 2) krylov_gemm(
    const __nv_bfloat16* __restrict__ th, const __nv_bfloat16* __restrict__ tm,
    const __nv_bfloat16* __restrict__ wth, const __nv_bfloat16* __restrict__ wtm,
    const float* __restrict__ bias, float* __restrict__ out, int n)
{
    extern __shared__ char smem[];
    char* sAh = smem;
    char* sAm = smem + TILE_BYTES;
    char* sBh = smem + 2 * TILE_BYTES;
    char* sBm = smem + 3 * TILE_BYTES;
    const uint32_t uAh = smem_u32(sAh), uAm = smem_u32(sAm);
    const uint32_t uBh = smem_u32(sBh), uBm = smem_u32(sBm);

    const int tid = threadIdx.x, lane = tid & 31, wid = tid >> 5;
    const int warp_m = (wid & 3) * 32;        // 4 warps along M
    const int warp_n = (wid >> 2) * 64;       // 2 warps along N
    const int r0 = blockIdx.x * 128;

    // ldmatrix per-lane address offsets (bytes)
    const int a_rin = (lane & 7) + ((lane >> 3) & 1) * 8;
    const int a_k8  = (lane >> 4);
    const int b_nrow = (lane & 7) + (lane >> 4) * 8;
    const int b_k8   = (lane >> 3) & 1;
    const uint32_t aoff0 = (uint32_t)((warp_m + a_rin) * A_STRB + a_k8 * 16);
    const uint32_t aoff1 = aoff0 + 16 * A_STRB;
    const uint32_t boffb = (uint32_t)((warp_n + b_nrow) * A_STRB + b_k8 * 16);

    float acc[2][4][2][4];
    #pragma unroll
    for (int i = 0; i < 2; i++)
        #pragma unroll
        for (int j = 0; j < 4; j++)
            #pragma unroll
            for (int k = 0; k < 2; k++)
                #pragma unroll
                for (int l = 0; l < 4; l++) acc[i][j][k][l] = 0.f;

    for (int kc = 0; kc < 1024; kc += 64) {
        const int term = kc >> 7;
        const int col0 = kc & 127;   // 0 or 64
        const __nv_bfloat16* Ah = th + ((size_t)term * NPAD + r0) * 128 + col0;
        const __nv_bfloat16* Am = tm + ((size_t)term * NPAD + r0) * 128 + col0;
        // A tiles: 128 rows x 64 cols -> 1024 uint4 per array, 4 per thread
        #pragma unroll
        for (int it = 0; it < 4; ++it) {
            int idx = tid + it * 256;
            int row = idx >> 3, q = idx & 7;
            uint32_t so = (uint32_t)(row * A_STRB + q * 16);
            *(uint4*)(sAh + so) = __ldg((const uint4*)(Ah + (size_t)row * 128) + q);
            *(uint4*)(sAm + so) = __ldg((const uint4*)(Am + (size_t)row * 128) + q);
        }
        // B tiles: 128 n-rows x 64 k -> 1024 uint4 per array
        #pragma unroll
        for (int it = 0; it < 4; ++it) {
            int idx = tid + it * 256;
            int nr = idx >> 3, q = idx & 7;
            uint32_t so = (uint32_t)(nr * A_STRB + q * 16);
            *(uint4*)(sBh + so) = __ldg((const uint4*)(wth + nr * 1024 + kc) + q);
            *(uint4*)(sBm + so) = __ldg((const uint4*)(wtm + nr * 1024 + kc) + q);
        }
        __syncthreads();
        #pragma unroll
        for (int ks = 0; ks < 4; ++ks) {
            const uint32_t kso = ks * 32;
            uint32_t ah0[4], ah1[4], am0[4], am1[4];
            ldsm4(ah0, uAh + aoff0 + kso);
            ldsm4(ah1, uAh + aoff1 + kso);
            ldsm4(am0, uAm + aoff0 + kso);
            ldsm4(am1, uAm + aoff1 + kso);
            #pragma unroll
            for (int np = 0; np < 4; ++np) {
                const uint32_t bo = boffb + np * 16 * A_STRB + kso;
                uint32_t bh[4], bm[4];
                ldsm4(bh, uBh + bo);
                mma16816(acc[0][np][0], ah0, bh + 0);
                mma16816(acc[0][np][1], ah0, bh + 2);
                mma16816(acc[1][np][0], ah1, bh + 0);
                mma16816(acc[1][np][1], ah1, bh + 2);
                mma16816(acc[0][np][0], am0, bh + 0);
                mma16816(acc[0][np][1], am0, bh + 2);
                mma16816(acc[1][np][0], am1, bh + 0);
                mma16816(acc[1][np][1], am1, bh + 2);
                ldsm4(bm, uBm + bo);
                mma16816(acc[0][np][0], ah0, bm + 0);
                mma16816(acc[0][np][1], ah0, bm + 2);
                mma16816(acc[1][np][0], ah1, bm + 0);
                mma16816(acc[1][np][1], ah1, bm + 2);
            }
        }
        __syncthreads();
    }

    // epilogue: D rows = warp_m + mb*16 + g (+8); cols = warp_n + np*16 + blk*8 + 2t
    const int g = lane >> 2, t4 = lane & 3;
    #pragma unroll
    for (int mb = 0; mb < 2; ++mb) {
        int r = r0 + warp_m + mb * 16 + g;
        #pragma unroll
        for (int np = 0; np < 4; ++np) {
            #pragma unroll
            for (int blk = 0; blk < 2; ++blk) {
                int col = warp_n + np * 16 + blk * 8 + 2 * t4;
                float b0 = __ldg(&bias[col]), b1 = __ldg(&bias[col + 1]);
                float* a = acc[mb][np][blk];
                if (r < n)
                    *(float2*)(out + (size_t)r * 128 + col) = make_float2(a[0] + b0, a[1] + b1);
                if (r + 8 < n)
                    *(float2*)(out + (size_t)(r + 8) * 128 + col) = make_float2(a[2] + b0, a[3] + b1);
            }
        }
    }
}

// ---------------- launch ----------------
extern "C" void kernel_launch(void* const* d_in, const int* in_sizes, int n_in,
                              void* d_out, int out_size) {
    const float* input = (const float*)d_in[0];
    const int*   esrc  = (const int*)d_in[1];
    const int*   edst  = (const int*)d_in[2];
    const float* ew    = (const float*)d_in[3];
    const float* W     = (const float*)d_in[4];
    const float* bias  = (const float*)d_in[5];
    float*       out   = (float*)d_out;

    int n = in_sizes[0] / F;
    int e = in_sizes[1];

    float *bufA = nullptr, *bufB = nullptr;
    __nv_bfloat16 *th = nullptr, *tm = nullptr, *wth = nullptr, *wtm = nullptr;
    cudaGetSymbolAddress((void**)&bufA, g_bufA);
    cudaGetSymbolAddress((void**)&bufB, g_bufB);
    cudaGetSymbolAddress((void**)&th, g_termsh);
    cudaGetSymbolAddress((void**)&tm, g_termsm);
    cudaGetSymbolAddress((void**)&wth, g_wth);
    cudaGetSymbolAddress((void**)&wtm, g_wtm);

    cudaFuncSetAttribute(krylov_gemm, cudaFuncAttributeMaxDynamicSharedMemorySize, SM_GEMM);

    // 1) CSR build
    zero_counts_kernel<<<(n + 255) / 256, 256>>>(n);
    hist_kernel<<<(e + 255) / 256, 256>>>(edst, e);
    scan_kernel<<<1, 1024>>>(n);
    scatter_kernel<<<(e + 255) / 256, 256>>>(esrc, edst, ew, e);

    // 2) W^T bf16 hi/mid + term0 conversion
    wprep_kernel<<<(1024 * 128 + 255) / 256, 256>>>(W);
    conv0_kernel<<<(n * 32 + 255) / 256, 256>>>(input, th, tm, n * 32);

    // 3) Krylov chain (fp32 ping-pong; bf16 h/m emitted per term)
    dim3 spmm_block(32, 8);
    int spmm_grid = (n + 7) / 8;
    const float* X = input;
    float* bufs[2] = {bufA, bufB};
    for (int t = 1; t < NBLK; ++t) {
        float* Y = bufs[t & 1];
        spmm_kernel<<<spmm_grid, spmm_block>>>(X, Y,
            th + (size_t)t * NPAD * F, tm + (size_t)t * NPAD * F, n);
        X = Y;
    }

    // 4) tensor-core GEMM + bias
    krylov_gemm<<<(n + 127) / 128, 256, SM_GEMM>>>(th, tm, wth, wtm, bias, out, n);
}